// round 1
// baseline (speedup 1.0000x reference)
#include <cuda_runtime.h>
#include <math.h>

#define L   4096
#define H   768
#define NH  12
#define HD  64

// Scratch for projected Q, K, V: [3][L][H] fp32 (~37.7 MB, static device array —
// allocation-free per harness rules).
__device__ float g_QKV[3][L * H];

// ---------------------------------------------------------------------------
// Kernel 1: Y = X @ W^T + b   (X:[L,H], W:[H,H] row-major, nn.Linear semantics)
// Tile: BM=64, BN=64, BK=16. 256 threads, 4x4 register tile each.
// Both A (X) and B (W) are K-major, stored transposed in smem ([k][row]) so the
// inner loop is two LDS.128 + 16 FFMA.
// ---------------------------------------------------------------------------
__global__ __launch_bounds__(256) void qkv_proj_kernel(
    const float* __restrict__ X,
    const float* __restrict__ W,
    const float* __restrict__ bias,
    int which)
{
    __shared__ float As[16][68];   // pad 4 -> conflict-free, float4-aligned
    __shared__ float Bs[16][68];

    float* __restrict__ Y = g_QKV[which];

    const int tid = threadIdx.x;
    const int tx  = tid & 15;
    const int ty  = tid >> 4;
    const int n0  = blockIdx.x * 64;
    const int m0  = blockIdx.y * 64;

    const int lrow = tid >> 2;          // 0..63
    const int lc4  = (tid & 3) * 4;     // 0,4,8,12

    const float* Xp = X + (size_t)(m0 + lrow) * H + lc4;
    const float* Wp = W + (size_t)(n0 + lrow) * H + lc4;

    float acc[4][4];
    #pragma unroll
    for (int i = 0; i < 4; i++)
        #pragma unroll
        for (int j = 0; j < 4; j++) acc[i][j] = 0.f;

    for (int k0 = 0; k0 < H; k0 += 16) {
        float4 xa = *(const float4*)(Xp + k0);
        float4 wa = *(const float4*)(Wp + k0);
        As[lc4 + 0][lrow] = xa.x; As[lc4 + 1][lrow] = xa.y;
        As[lc4 + 2][lrow] = xa.z; As[lc4 + 3][lrow] = xa.w;
        Bs[lc4 + 0][lrow] = wa.x; Bs[lc4 + 1][lrow] = wa.y;
        Bs[lc4 + 2][lrow] = wa.z; Bs[lc4 + 3][lrow] = wa.w;
        __syncthreads();

        #pragma unroll
        for (int kk = 0; kk < 16; kk++) {
            float4 a = *(const float4*)(&As[kk][ty * 4]);
            float4 b = *(const float4*)(&Bs[kk][tx * 4]);
            float av[4] = {a.x, a.y, a.z, a.w};
            float bv[4] = {b.x, b.y, b.z, b.w};
            #pragma unroll
            for (int i = 0; i < 4; i++)
                #pragma unroll
                for (int j = 0; j < 4; j++)
                    acc[i][j] = fmaf(av[i], bv[j], acc[i][j]);
        }
        __syncthreads();
    }

    const int orow = m0 + ty * 4;
    const int ocol = n0 + tx * 4;
    float4 bb = *(const float4*)(&bias[ocol]);
    #pragma unroll
    for (int i = 0; i < 4; i++) {
        float4 r;
        r.x = acc[i][0] + bb.x;
        r.y = acc[i][1] + bb.y;
        r.z = acc[i][2] + bb.z;
        r.w = acc[i][3] + bb.w;
        *(float4*)(&Y[(size_t)(orow + i) * H + ocol]) = r;
    }
}

// ---------------------------------------------------------------------------
// Kernel 2: flash attention, one (head, 64-row q-tile) per block.
// K-tile = 32 cols. Online softmax with shuffle reductions across 16 lanes
// (thread layout 16x16: ty = 4 q-rows, tx = 2 score-cols / 4 out-cols).
// Smem: Qs[d][r], Ks[d][c] (transposed for QK^T), Vs[c][d], Ps[c][r]
// (transposed for P·V) — all inner loops are vector LDS + FFMA.
// ---------------------------------------------------------------------------
__global__ __launch_bounds__(256) void flash_attn_kernel(
    const float* __restrict__ mask,
    float* __restrict__ out)
{
    __shared__ float Qs[64][68];   // [d][r]
    __shared__ float Ks[64][36];   // [d][c]
    __shared__ float Vs[32][68];   // [c][d]
    __shared__ float Ps[32][68];   // [c][r]

    const float* __restrict__ Q = g_QKV[0];
    const float* __restrict__ K = g_QKV[1];
    const float* __restrict__ V = g_QKV[2];

    const int tid = threadIdx.x;
    const int tx  = tid & 15;
    const int ty  = tid >> 4;
    const int h   = blockIdx.y;
    const int q0  = blockIdx.x * 64;
    const int hc  = h * HD;

    // Load Q tile transposed: Qs[d][r]
    #pragma unroll
    for (int i = 0; i < 4; i++) {
        int idx = tid + i * 256;         // 0..1023
        int r   = idx >> 4;              // 0..63
        int g   = (idx & 15) * 4;        // d group
        float4 v = *(const float4*)(&Q[(size_t)(q0 + r) * H + hc + g]);
        Qs[g + 0][r] = v.x; Qs[g + 1][r] = v.y;
        Qs[g + 2][r] = v.z; Qs[g + 3][r] = v.w;
    }

    float m_i[4], l_i[4], o[4][4];
    #pragma unroll
    for (int i = 0; i < 4; i++) {
        m_i[i] = -INFINITY;
        l_i[i] = 0.f;
        #pragma unroll
        for (int j = 0; j < 4; j++) o[i][j] = 0.f;
    }

    const float scale = 0.125f;   // 1/sqrt(64)

    for (int k0 = 0; k0 < L; k0 += 32) {
        __syncthreads();   // covers initial Q load and protects Ks/Vs/Ps reuse

        // Load K tile (transposed) and V tile
        #pragma unroll
        for (int i = 0; i < 2; i++) {
            int idx = tid + i * 256;     // 0..511
            int c   = idx >> 4;          // 0..31
            int g   = (idx & 15) * 4;
            float4 kv = *(const float4*)(&K[(size_t)(k0 + c) * H + hc + g]);
            Ks[g + 0][c] = kv.x; Ks[g + 1][c] = kv.y;
            Ks[g + 2][c] = kv.z; Ks[g + 3][c] = kv.w;
            float4 vv = *(const float4*)(&V[(size_t)(k0 + c) * H + hc + g]);
            *(float4*)(&Vs[c][g]) = vv;
        }
        __syncthreads();

        // S[64x32] tile: s[i][j] for rows 4ty+i, cols 2tx+j
        float s[4][2];
        #pragma unroll
        for (int i = 0; i < 4; i++) { s[i][0] = 0.f; s[i][1] = 0.f; }

        #pragma unroll
        for (int d = 0; d < 64; d++) {
            float4 a = *(const float4*)(&Qs[d][ty * 4]);
            float2 b = *(const float2*)(&Ks[d][tx * 2]);
            float av[4] = {a.x, a.y, a.z, a.w};
            #pragma unroll
            for (int i = 0; i < 4; i++) {
                s[i][0] = fmaf(av[i], b.x, s[i][0]);
                s[i][1] = fmaf(av[i], b.y, s[i][1]);
            }
        }

        float mk0 = mask[k0 + tx * 2 + 0];
        float mk1 = mask[k0 + tx * 2 + 1];

        float p[4][2];
        #pragma unroll
        for (int i = 0; i < 4; i++) {
            s[i][0] = fmaf(s[i][0], scale, mk0);
            s[i][1] = fmaf(s[i][1], scale, mk1);

            float rm = fmaxf(s[i][0], s[i][1]);
            #pragma unroll
            for (int off = 1; off < 16; off <<= 1)
                rm = fmaxf(rm, __shfl_xor_sync(0xffffffffu, rm, off));

            float mn    = fmaxf(m_i[i], rm);
            float alpha = __expf(m_i[i] - mn);
            p[i][0] = __expf(s[i][0] - mn);
            p[i][1] = __expf(s[i][1] - mn);

            float rs = p[i][0] + p[i][1];
            #pragma unroll
            for (int off = 1; off < 16; off <<= 1)
                rs += __shfl_xor_sync(0xffffffffu, rs, off);

            l_i[i] = l_i[i] * alpha + rs;
            m_i[i] = mn;
            #pragma unroll
            for (int j = 0; j < 4; j++) o[i][j] *= alpha;
        }

        // Store P transposed: Ps[c][r]
        #pragma unroll
        for (int j = 0; j < 2; j++)
            #pragma unroll
            for (int i = 0; i < 4; i++)
                Ps[tx * 2 + j][ty * 4 + i] = p[i][j];
        __syncthreads();

        // O += P · V : o[i][j] over rows 4ty+i, d-cols 4tx+j
        #pragma unroll
        for (int c = 0; c < 32; c++) {
            float4 a = *(const float4*)(&Ps[c][ty * 4]);
            float4 b = *(const float4*)(&Vs[c][tx * 4]);
            float av[4] = {a.x, a.y, a.z, a.w};
            float bv[4] = {b.x, b.y, b.z, b.w};
            #pragma unroll
            for (int i = 0; i < 4; i++)
                #pragma unroll
                for (int j = 0; j < 4; j++)
                    o[i][j] = fmaf(av[i], bv[j], o[i][j]);
        }
    }

    // Epilogue: normalize and write out[(q0+r), h*64 + d]
    #pragma unroll
    for (int i = 0; i < 4; i++) {
        float inv = 1.f / l_i[i];
        float4 r;
        r.x = o[i][0] * inv;
        r.y = o[i][1] * inv;
        r.z = o[i][2] * inv;
        r.w = o[i][3] * inv;
        *(float4*)(&out[(size_t)(q0 + ty * 4 + i) * H + hc + tx * 4]) = r;
    }
}

// ---------------------------------------------------------------------------
extern "C" void kernel_launch(void* const* d_in, const int* in_sizes, int n_in,
                              void* d_out, int out_size)
{
    const float* query = (const float*)d_in[0];
    const float* key   = (const float*)d_in[1];
    const float* value = (const float*)d_in[2];
    const float* mask  = (const float*)d_in[3];
    const float* Wq    = (const float*)d_in[4];
    const float* bq    = (const float*)d_in[5];
    const float* Wk    = (const float*)d_in[6];
    const float* bk    = (const float*)d_in[7];
    const float* Wv    = (const float*)d_in[8];
    const float* bv    = (const float*)d_in[9];
    float* out = (float*)d_out;

    dim3 pg(H / 64, L / 64);   // 12 x 64
    qkv_proj_kernel<<<pg, 256>>>(query, Wq, bq, 0);
    qkv_proj_kernel<<<pg, 256>>>(key,   Wk, bk, 1);
    qkv_proj_kernel<<<pg, 256>>>(value, Wv, bv, 2);

    dim3 ag(L / 64, NH);       // 64 x 12
    flash_attn_kernel<<<ag, 256>>>(mask, out);
}

// round 3
// speedup vs baseline: 2.7076x; 2.7076x over previous
#include <cuda_runtime.h>
#include <math.h>
#include <stdint.h>

#define L   4096
#define H   768
#define NH  12
#define HD  64

// Projected Q, K, V (tf32-rounded fp32): [3][L][H]. Static device scratch.
__device__ float g_QKV[3][L * H];

// ===========================================================================
// helpers
// ===========================================================================
__device__ __forceinline__ uint32_t smem_u32(const void* p) {
    uint32_t a;
    asm("{ .reg .u64 t; cvta.to.shared.u64 t, %1; cvt.u32.u64 %0, t; }" : "=r"(a) : "l"(p));
    return a;
}

// m16n8k8 tf32 mma (sm_80+; assembles for compute_103).
// A row-major 16x8, B col-major 8x8 (b0=(k=t,n=g), b1=(k=t+4,n=g)), C/D f32.
__device__ __forceinline__ void mma_tf32(float c[4],
                                         uint32_t a0, uint32_t a1, uint32_t a2, uint32_t a3,
                                         uint32_t b0, uint32_t b1) {
    asm volatile(
        "mma.sync.aligned.m16n8k8.row.col.f32.tf32.tf32.f32 "
        "{%0,%1,%2,%3}, {%4,%5,%6,%7}, {%8,%9}, {%0,%1,%2,%3};"
        : "+f"(c[0]), "+f"(c[1]), "+f"(c[2]), "+f"(c[3])
        : "r"(a0), "r"(a1), "r"(a2), "r"(a3), "r"(b0), "r"(b1));
}

__device__ __forceinline__ uint32_t cvt_tf32(float x) {   // RNA round, valid fp32 bits
    uint32_t u; asm("cvt.rna.tf32.f32 %0, %1;" : "=r"(u) : "f"(x)); return u;
}

#define CP16(dst, src) \
    asm volatile("cp.async.cg.shared.global [%0], [%1], 16;" :: "r"(dst), "l"(src))
#define CP_COMMIT()  asm volatile("cp.async.commit_group;")
#define CP_WAIT0()   asm volatile("cp.async.wait_group 0;")
#define CP_WAIT1()   asm volatile("cp.async.wait_group 1;")

// exp(x) for x <= 0 with NO MUFU: 2^(x*log2e) via magic-number round + deg-5 poly.
__device__ __forceinline__ float expfast(float x) {
    x = fmaxf(x, -80.0f);
    const float L2E   = 1.4426950408889634f;
    const float MAGIC = 12582912.0f;            // 1.5 * 2^23
    float tt = fmaf(x, L2E, MAGIC);
    int   ji = __float_as_int(tt) << 23;        // j * 2^23 (two's complement low bits)
    float jf = tt - MAGIC;
    float f  = fmaf(x, L2E, -jf);               // f in [-0.5, 0.5]
    float p  = 1.3333558146e-3f;
    p = fmaf(p, f, 9.6181291076e-3f);
    p = fmaf(p, f, 5.5504108664e-2f);
    p = fmaf(p, f, 2.4022650696e-1f);
    p = fmaf(p, f, 6.9314718056e-1f);
    p = fmaf(p, f, 1.0f);
    return __int_as_float(__float_as_int(p) + ji);
}

// ===========================================================================
// Kernel 1: QKV projection, mma.sync tf32 with 3xTF32 split (fp32 accuracy).
// Y = X @ W^T + b, output RNA-rounded to tf32 (it is only consumed by tf32 mma).
// Block 256 thr (8 warps, 4x2), tile 128x128, BK=32, cp.async double-buffered.
// ===========================================================================
#define P_AS(buf) ((buf) * 4608)           // [128][36] floats
#define P_BS(buf) (9216 + (buf) * 4608)
#define PROJ_SMEM_F 18432                  // floats
#define PROJ_SMEM_B (PROJ_SMEM_F * 4)      // 73728 bytes

__global__ __launch_bounds__(256, 1) void qkv_proj_tc(
    const float* __restrict__ Xq, const float* __restrict__ Xk, const float* __restrict__ Xv,
    const float* __restrict__ Wq, const float* __restrict__ Wk, const float* __restrict__ Wv,
    const float* __restrict__ bq, const float* __restrict__ bk, const float* __restrict__ bv)
{
    extern __shared__ float sm[];
    const uint32_t smb = smem_u32(sm);

    const int tid  = threadIdx.x;
    const int w    = tid >> 5, lane = tid & 31;
    const int g    = lane >> 2, t = lane & 3;
    const int wm   = w & 3, wn = w >> 2;
    const int z    = blockIdx.z;
    const int n0   = blockIdx.x * 128;
    const int m0   = blockIdx.y * 128;

    const float* X    = (z == 0) ? Xq : (z == 1) ? Xk : Xv;
    const float* W    = (z == 0) ? Wq : (z == 1) ? Wk : Wv;
    const float* bias = (z == 0) ? bq : (z == 1) ? bk : bv;
    float* Y = g_QKV[z];

    float acc[2][8][4];
    #pragma unroll
    for (int mt = 0; mt < 2; mt++)
        #pragma unroll
        for (int nt = 0; nt < 8; nt++)
            #pragma unroll
            for (int j = 0; j < 4; j++) acc[mt][nt][j] = 0.f;

    auto load_tile = [&](int kt, int buf) {
        #pragma unroll
        for (int i = 0; i < 4; i++) {
            int id = tid + i * 256;          // 0..1023
            int r  = id >> 3;                // 0..127
            int c  = (id & 7) * 4;           // 0..28
            CP16(smb + (P_AS(buf) + r * 36 + c) * 4,
                 X + (size_t)(m0 + r) * H + kt * 32 + c);
            CP16(smb + (P_BS(buf) + r * 36 + c) * 4,
                 W + (size_t)(n0 + r) * H + kt * 32 + c);
        }
    };

    load_tile(0, 0);
    CP_COMMIT();

    #pragma unroll 1
    for (int kt = 0; kt < 24; kt++) {
        const int buf = kt & 1;
        if (kt < 23) { load_tile(kt + 1, buf ^ 1); CP_COMMIT(); CP_WAIT1(); }
        else         { CP_WAIT0(); }
        __syncthreads();

        const float* As = sm + P_AS(buf);
        const float* Bs = sm + P_BS(buf);

        #pragma unroll
        for (int ks = 0; ks < 4; ks++) {
            uint32_t ab[2][4], asml[2][4];
            #pragma unroll
            for (int mt = 0; mt < 2; mt++) {
                const float* A0 = As + (32 * wm + 16 * mt + g) * 36 + 8 * ks;
                float a0 = A0[t], a1 = A0[8 * 36 + t], a2 = A0[t + 4], a3 = A0[8 * 36 + t + 4];
                ab[mt][0] = cvt_tf32(a0); asml[mt][0] = cvt_tf32(a0 - __uint_as_float(ab[mt][0]));
                ab[mt][1] = cvt_tf32(a1); asml[mt][1] = cvt_tf32(a1 - __uint_as_float(ab[mt][1]));
                ab[mt][2] = cvt_tf32(a2); asml[mt][2] = cvt_tf32(a2 - __uint_as_float(ab[mt][2]));
                ab[mt][3] = cvt_tf32(a3); asml[mt][3] = cvt_tf32(a3 - __uint_as_float(ab[mt][3]));
            }
            uint32_t bb0[8], bb1[8], bs0[8], bs1[8];
            #pragma unroll
            for (int nt = 0; nt < 8; nt++) {
                const float* B0 = Bs + (64 * wn + 8 * nt + g) * 36 + 8 * ks;
                float b0 = B0[t], b1 = B0[t + 4];
                bb0[nt] = cvt_tf32(b0); bs0[nt] = cvt_tf32(b0 - __uint_as_float(bb0[nt]));
                bb1[nt] = cvt_tf32(b1); bs1[nt] = cvt_tf32(b1 - __uint_as_float(bb1[nt]));
            }
            #pragma unroll
            for (int mt = 0; mt < 2; mt++)
                #pragma unroll
                for (int nt = 0; nt < 8; nt++) {
                    mma_tf32(acc[mt][nt], ab[mt][0], ab[mt][1], ab[mt][2], ab[mt][3], bb0[nt], bb1[nt]);
                    mma_tf32(acc[mt][nt], ab[mt][0], ab[mt][1], ab[mt][2], ab[mt][3], bs0[nt], bs1[nt]);
                    mma_tf32(acc[mt][nt], asml[mt][0], asml[mt][1], asml[mt][2], asml[mt][3], bb0[nt], bb1[nt]);
                }
        }
        __syncthreads();
    }

    // Epilogue: +bias, RNA-round to tf32, store.
    #pragma unroll
    for (int mt = 0; mt < 2; mt++) {
        int row = m0 + 32 * wm + 16 * mt + g;
        #pragma unroll
        for (int nt = 0; nt < 8; nt++) {
            int col = n0 + 64 * wn + 8 * nt + 2 * t;
            float2 bv2 = *(const float2*)&bias[col];
            float2 y0, y1;
            y0.x = __uint_as_float(cvt_tf32(acc[mt][nt][0] + bv2.x));
            y0.y = __uint_as_float(cvt_tf32(acc[mt][nt][1] + bv2.y));
            y1.x = __uint_as_float(cvt_tf32(acc[mt][nt][2] + bv2.x));
            y1.y = __uint_as_float(cvt_tf32(acc[mt][nt][3] + bv2.y));
            *(float2*)&Y[(size_t)row * H + col]       = y0;
            *(float2*)&Y[(size_t)(row + 8) * H + col] = y1;
        }
    }
}

// ===========================================================================
// Kernel 2: flash attention on mma.sync tf32.
// Block: 128 q-rows x 1 head, 8 warps; warp w owns rows [16w, 16w+16).
// Bc=64 kv per iter; Q register-resident A-frags; S & PV on tensor cores;
// polynomial exp (no MUFU); P via per-warp smem (syncwarp only).
// smem (floats): Ms[2][64] @0, Ks[2][64][68] @128, Vs[2][64][68] @8832, Ps[128][68] @17536.
// ===========================================================================
#define F_MS(buf)  ((buf) * 64)
#define F_KS(buf)  (128 + (buf) * 4352)
#define F_VS(buf)  (8832 + (buf) * 4352)
#define F_PS       17536
#define FLASH_SMEM_F 26240
#define FLASH_SMEM_B (FLASH_SMEM_F * 4)    // 104960 bytes

__global__ __launch_bounds__(256, 1) void flash_attn_tc(
    const float* __restrict__ mask,
    float* __restrict__ out)
{
    extern __shared__ float sm[];
    const uint32_t smb = smem_u32(sm);

    const int tid  = threadIdx.x;
    const int w    = tid >> 5, lane = tid & 31;
    const int g    = lane >> 2, t = lane & 3;
    const int h    = blockIdx.y;
    const int q0   = blockIdx.x * 128;
    const int hc   = h * HD;

    const float* Qg = g_QKV[0];
    const float* Kg = g_QKV[1];
    const float* Vg = g_QKV[2];

    // Q A-fragments, register resident for the whole kv loop (values already tf32).
    uint32_t qa[8][4];
    {
        const float* q0p = Qg + (size_t)(q0 + 16 * w + g) * H + hc;
        const float* q1p = q0p + 8 * H;
        #pragma unroll
        for (int kk = 0; kk < 8; kk++) {
            qa[kk][0] = __float_as_uint(q0p[8 * kk + t]);
            qa[kk][1] = __float_as_uint(q1p[8 * kk + t]);
            qa[kk][2] = __float_as_uint(q0p[8 * kk + t + 4]);
            qa[kk][3] = __float_as_uint(q1p[8 * kk + t + 4]);
        }
    }

    float o[8][4];
    #pragma unroll
    for (int nt = 0; nt < 8; nt++)
        #pragma unroll
        for (int j = 0; j < 4; j++) o[nt][j] = 0.f;
    float m0 = -INFINITY, m1 = -INFINITY, l0 = 0.f, l1 = 0.f;

    auto load_kv = [&](int it, int buf) {
        const int k0 = it * 64;
        #pragma unroll
        for (int i = 0; i < 4; i++) {
            int id = tid + i * 256;          // 0..1023
            int r  = id >> 4;                // 0..63
            int c  = (id & 15) * 4;          // 0..60
            CP16(smb + (F_KS(buf) + r * 68 + c) * 4, Kg + (size_t)(k0 + r) * H + hc + c);
            CP16(smb + (F_VS(buf) + r * 68 + c) * 4, Vg + (size_t)(k0 + r) * H + hc + c);
        }
        if (tid < 16) CP16(smb + (F_MS(buf) + tid * 4) * 4, mask + k0 + tid * 4);
    };

    load_kv(0, 0);
    CP_COMMIT();

    float* Psw = sm + F_PS + (16 * w) * 68;   // this warp's 16-row P region

    #pragma unroll 1
    for (int it = 0; it < L / 64; it++) {
        const int buf = it & 1;
        if (it < L / 64 - 1) { load_kv(it + 1, buf ^ 1); CP_COMMIT(); CP_WAIT1(); }
        else                 { CP_WAIT0(); }
        __syncthreads();

        const float* Ks = sm + F_KS(buf);
        const float* Vs = sm + F_VS(buf);
        const float* Ms = sm + F_MS(buf);

        // ---- S = Q K^T (16 x 64 per warp) ----
        float s[8][4];
        #pragma unroll
        for (int nt = 0; nt < 8; nt++)
            #pragma unroll
            for (int j = 0; j < 4; j++) s[nt][j] = 0.f;

        #pragma unroll
        for (int kk = 0; kk < 8; kk++) {
            uint32_t kb0[8], kb1[8];
            #pragma unroll
            for (int nt = 0; nt < 8; nt++) {
                const float* kp = Ks + (8 * nt + g) * 68 + 8 * kk;
                kb0[nt] = __float_as_uint(kp[t]);
                kb1[nt] = __float_as_uint(kp[t + 4]);
            }
            #pragma unroll
            for (int nt = 0; nt < 8; nt++)
                mma_tf32(s[nt], qa[kk][0], qa[kk][1], qa[kk][2], qa[kk][3], kb0[nt], kb1[nt]);
        }

        // ---- scale + mask, online softmax ----
        float rmx0 = -INFINITY, rmx1 = -INFINITY;
        #pragma unroll
        for (int nt = 0; nt < 8; nt++) {
            float2 mk = *(const float2*)&Ms[8 * nt + 2 * t];
            s[nt][0] = fmaf(s[nt][0], 0.125f, mk.x);
            s[nt][1] = fmaf(s[nt][1], 0.125f, mk.y);
            s[nt][2] = fmaf(s[nt][2], 0.125f, mk.x);
            s[nt][3] = fmaf(s[nt][3], 0.125f, mk.y);
            rmx0 = fmaxf(rmx0, fmaxf(s[nt][0], s[nt][1]));
            rmx1 = fmaxf(rmx1, fmaxf(s[nt][2], s[nt][3]));
        }
        rmx0 = fmaxf(rmx0, __shfl_xor_sync(0xffffffffu, rmx0, 1));
        rmx0 = fmaxf(rmx0, __shfl_xor_sync(0xffffffffu, rmx0, 2));
        rmx1 = fmaxf(rmx1, __shfl_xor_sync(0xffffffffu, rmx1, 1));
        rmx1 = fmaxf(rmx1, __shfl_xor_sync(0xffffffffu, rmx1, 2));

        float mn0 = fmaxf(m0, rmx0), mn1 = fmaxf(m1, rmx1);
        float al0 = expfast(m0 - mn0), al1 = expfast(m1 - mn1);
        m0 = mn0; m1 = mn1;

        float rs0 = 0.f, rs1 = 0.f;
        #pragma unroll
        for (int nt = 0; nt < 8; nt++) {
            float p0 = expfast(s[nt][0] - mn0);
            float p1 = expfast(s[nt][1] - mn0);
            float p2 = expfast(s[nt][2] - mn1);
            float p3 = expfast(s[nt][3] - mn1);
            rs0 += p0 + p1;
            rs1 += p2 + p3;
            float2 v0, v1;                       // RNA-round P for unbiased PV mma
            v0.x = __uint_as_float(cvt_tf32(p0));
            v0.y = __uint_as_float(cvt_tf32(p1));
            v1.x = __uint_as_float(cvt_tf32(p2));
            v1.y = __uint_as_float(cvt_tf32(p3));
            *(float2*)&Psw[g * 68 + 8 * nt + 2 * t]       = v0;
            *(float2*)&Psw[(g + 8) * 68 + 8 * nt + 2 * t] = v1;
        }
        rs0 += __shfl_xor_sync(0xffffffffu, rs0, 1);
        rs0 += __shfl_xor_sync(0xffffffffu, rs0, 2);
        rs1 += __shfl_xor_sync(0xffffffffu, rs1, 1);
        rs1 += __shfl_xor_sync(0xffffffffu, rs1, 2);
        l0 = l0 * al0 + rs0;
        l1 = l1 * al1 + rs1;

        #pragma unroll
        for (int nt = 0; nt < 8; nt++) {
            o[nt][0] *= al0; o[nt][1] *= al0;
            o[nt][2] *= al1; o[nt][3] *= al1;
        }
        __syncwarp();

        // ---- O += P V (16 x 64 per warp) ----
        #pragma unroll
        for (int kk = 0; kk < 8; kk++) {
            uint32_t a0 = __float_as_uint(Psw[g * 68 + 8 * kk + t]);
            uint32_t a1 = __float_as_uint(Psw[(g + 8) * 68 + 8 * kk + t]);
            uint32_t a2 = __float_as_uint(Psw[g * 68 + 8 * kk + t + 4]);
            uint32_t a3 = __float_as_uint(Psw[(g + 8) * 68 + 8 * kk + t + 4]);
            #pragma unroll
            for (int nt = 0; nt < 8; nt++) {
                uint32_t b0 = __float_as_uint(Vs[(8 * kk + t) * 68 + 8 * nt + g]);
                uint32_t b1 = __float_as_uint(Vs[(8 * kk + t + 4) * 68 + 8 * nt + g]);
                mma_tf32(o[nt], a0, a1, a2, a3, b0, b1);
            }
        }
        __syncthreads();
    }

    // ---- epilogue ----
    const float inv0 = 1.0f / l0, inv1 = 1.0f / l1;
    const int row = q0 + 16 * w + g;
    #pragma unroll
    for (int nt = 0; nt < 8; nt++) {
        int col = hc + 8 * nt + 2 * t;
        float2 r0, r1;
        r0.x = o[nt][0] * inv0; r0.y = o[nt][1] * inv0;
        r1.x = o[nt][2] * inv1; r1.y = o[nt][3] * inv1;
        *(float2*)&out[(size_t)row * H + col]       = r0;
        *(float2*)&out[(size_t)(row + 8) * H + col] = r1;
    }
}

// ---------------------------------------------------------------------------
extern "C" void kernel_launch(void* const* d_in, const int* in_sizes, int n_in,
                              void* d_out, int out_size)
{
    const float* query = (const float*)d_in[0];
    const float* key   = (const float*)d_in[1];
    const float* value = (const float*)d_in[2];
    const float* mask  = (const float*)d_in[3];
    const float* Wq    = (const float*)d_in[4];
    const float* bq    = (const float*)d_in[5];
    const float* Wk    = (const float*)d_in[6];
    const float* bk    = (const float*)d_in[7];
    const float* Wv    = (const float*)d_in[8];
    const float* bv    = (const float*)d_in[9];
    float* out = (float*)d_out;

    cudaFuncSetAttribute(qkv_proj_tc,  cudaFuncAttributeMaxDynamicSharedMemorySize, PROJ_SMEM_B);
    cudaFuncSetAttribute(flash_attn_tc, cudaFuncAttributeMaxDynamicSharedMemorySize, FLASH_SMEM_B);

    dim3 pg(H / 128, L / 128, 3);    // 6 x 32 x 3
    qkv_proj_tc<<<pg, 256, PROJ_SMEM_B>>>(query, key, value, Wq, Wk, Wv, bq, bk, bv);

    dim3 ag(L / 128, NH);            // 32 x 12
    flash_attn_tc<<<ag, 256, FLASH_SMEM_B>>>(mask, out);
}